// round 6
// baseline (speedup 1.0000x reference)
#include <cuda_runtime.h>

#define C_DIM   64
#define TPB     128
#define MARGIN_F 0.01f
#define MAX_BLOCKS 8192

using u64 = unsigned long long;

// ---- compile-time weights ----
__host__ __device__ constexpr float W2f(int i)  { return 0.5f / (float)(C_DIM - i); }
__host__ __device__ constexpr float CPXf(int x) { return -(W2f(x + 1) + W2f(63 - x)); }
__host__ __device__ constexpr float W2SUMf() {
    float s = 0.0f;
    for (int i = 1; i < C_DIM; i++) s += W2f(i);
    return s;
}

__device__ float        g_partials[MAX_BLOCKS];
__device__ unsigned int g_sem = 0;

// ---- packed f32x2 helpers (Blackwell) ----
__device__ __forceinline__ u64 pk2(float lo, float hi) {
    u64 r;
    asm("mov.b64 %0, {%1, %2};" : "=l"(r) : "f"(lo), "f"(hi));
    return r;
}
__device__ __forceinline__ void upk2(u64 v, float& lo, float& hi) {
    asm("mov.b64 {%0, %1}, %2;" : "=f"(lo), "=f"(hi) : "l"(v));
}
__device__ __forceinline__ u64 fma2(u64 a, u64 b, u64 c) {
    u64 r;
    asm("fma.rn.f32x2 %0, %1, %2, %3;" : "=l"(r) : "l"(a), "l"(b), "l"(c));
    return r;
}
__device__ __forceinline__ u64 add2(u64 a, u64 b) {
    u64 r;
    asm("add.rn.f32x2 %0, %1, %2;" : "=l"(r) : "l"(a), "l"(b));
    return r;
}
__device__ __forceinline__ u64 abs2(u64 a) {
    return a & 0x7FFFFFFF7FFFFFFFULL;   // 2x LOP3, alu pipe
}
// duplicate a (compile-time-constant) float into both packed lanes
__device__ __forceinline__ u64 dup2(float f) {
    unsigned u = __float_as_uint(f);
    return (u64)u * 0x100000001ULL;     // constant-folds to mov.b64 imm
}

__global__ void __launch_bounds__(TPB)
margin_loss_kernel(const float* __restrict__ cand,
                   const float* __restrict__ summ,
                   float* __restrict__ out,
                   int B, int H, float invB)
{
    const int t = blockIdx.x * TPB + threadIdx.x;

    float thread_total = 0.0f;

    if (t < H) {
        const int  rowA = t;
        const int  rowB = t + H;
        const bool hasB = (rowB < B);
        const int  rB   = hasB ? rowB : rowA;

        const float4* pa = reinterpret_cast<const float4*>(cand + (size_t)rowA * C_DIM);
        const float4* pb = reinterpret_cast<const float4*>(cand + (size_t)rB   * C_DIM);

        const u64 s2   = pk2(summ[rowA], summ[rB]);
        const u64 NEG1 = dup2(-1.0f);

        u64 P[C_DIM];
        u64 sa = 0ULL;   // packed sum of |cs - s|
        u64 p  = 0ULL;   // packed running prefix sum of margin-folded values
        u64 an = 0ULL;   // packed telescoped analytic accumulator

        // ---- load + pack + summary-abs + margin-fold + prefix, streamed ----
        #pragma unroll
        for (int i = 0; i < C_DIM / 4; i++) {
            float4 va = pa[i];
            float4 vb = pb[i];
            #pragma unroll
            for (int k = 0; k < 4; k++) {
                const int x = 4 * i + k;
                float av = (k == 0) ? va.x : (k == 1) ? va.y : (k == 2) ? va.z : va.w;
                float bv = (k == 0) ? vb.x : (k == 1) ? vb.y : (k == 2) ? vb.z : vb.w;
                u64 v = pk2(av, bv);                    // unfolded scores

                // summary: accumulate |cs - s|
                u64 d = fma2(s2, NEG1, v);              // v - s
                sa = add2(sa, abs2(d));

                // fold margin: a[x] = cs[x] + 0.01*x
                v = add2(v, dup2(MARGIN_F * (float)x));
                P[x] = v;

                // prefix + telescope coefficient
                p = add2(p, v);
                if (x < 63)
                    an = fma2(dup2(CPXf(x)), p, an);
            }
        }

        // ---- scalar epilogue of analytic parts ----
        float pA, pB, saA, saB, anA, anB, ssA, ssB;
        upk2(p,  pA,  pB);
        upk2(sa, saA, saB);
        upk2(an, anA, anB);
        upk2(s2, ssA, ssB);

        // sum of margin offsets: sum_{x=0}^{63} 0.01*x = 20.16
        const float MOFF = 20.16f;
        // summary term: (1/(2C)) * ( sum|cs-s| + sum(cs) - C*s )
        float tA = (saA + (pA - MOFF) - 64.0f * ssA) * (0.5f / 64.0f);
        float tB = (saB + (pB - MOFF) - 64.0f * ssB) * (0.5f / 64.0f);
        // telescoped sum_i w2(i)*T_i = an + S_folded * w2sum
        tA += anA + pA * W2SUMf();
        tB += anB + pB * W2SUMf();

        // ---- core: packed |a[j+i] - a[j]| over all gaps, both rows at once ----
        #pragma unroll
        for (int i = 1; i < C_DIM; i++) {
            u64 g0 = 0ULL, g1 = 0ULL, g2 = 0ULL;
            #pragma unroll
            for (int j = 0; j + i < C_DIM; j += 3) {
                g0 = add2(g0, abs2(fma2(P[j], NEG1, P[j + i])));
                if (j + 1 + i < C_DIM)
                    g1 = add2(g1, abs2(fma2(P[j + 1], NEG1, P[j + 1 + i])));
                if (j + 2 + i < C_DIM)
                    g2 = add2(g2, abs2(fma2(P[j + 2], NEG1, P[j + 2 + i])));
            }
            u64 g = add2(add2(g0, g1), g2);
            float glo, ghi;
            upk2(g, glo, ghi);
            tA = __fmaf_rn(glo, W2f(i), tA);   // FFMA-immediate, rt=1
            tB = __fmaf_rn(ghi, W2f(i), tB);
        }

        thread_total = tA + (hasB ? tB : 0.0f);
    }

    // ---- deterministic block reduction ----
    __shared__ float sred[TPB];
    __shared__ bool  amLast;
    sred[threadIdx.x] = thread_total;
    __syncthreads();
    #pragma unroll
    for (int off = TPB / 2; off > 0; off >>= 1) {
        if (threadIdx.x < off)
            sred[threadIdx.x] += sred[threadIdx.x + off];
        __syncthreads();
    }
    if (threadIdx.x == 0) {
        g_partials[blockIdx.x] = sred[0];
        __threadfence();
        unsigned int v = atomicAdd(&g_sem, 1u);
        amLast = (v == gridDim.x - 1);
    }
    __syncthreads();

    // ---- last arriving block: deterministic final reduce ----
    if (amLast) {
        float v = 0.0f;
        for (int i = threadIdx.x; i < (int)gridDim.x; i += TPB)
            v += g_partials[i];
        sred[threadIdx.x] = v;
        __syncthreads();
        #pragma unroll
        for (int off = TPB / 2; off > 0; off >>= 1) {
            if (threadIdx.x < off)
                sred[threadIdx.x] += sred[threadIdx.x + off];
            __syncthreads();
        }
        if (threadIdx.x == 0) {
            out[0] = sred[0] * invB;
            g_sem = 0;   // reset for next graph replay
        }
    }
}

extern "C" void kernel_launch(void* const* d_in, const int* in_sizes, int n_in,
                              void* d_out, int out_size)
{
    const float* cand = (const float*)d_in[0];   // [B, 64] f32
    const float* summ = (const float*)d_in[1];   // [B]     f32
    float* out = (float*)d_out;

    const int B = in_sizes[1];
    const int H = (B + 1) / 2;                   // rows per half; thread t -> rows t, t+H
    int nblocks = (H + TPB - 1) / TPB;
    if (nblocks > MAX_BLOCKS) nblocks = MAX_BLOCKS;
    const float invB = 1.0f / (float)B;

    margin_loss_kernel<<<nblocks, TPB>>>(cand, summ, out, B, H, invB);
}

// round 9
// speedup vs baseline: 1.7860x; 1.7860x over previous
#include <cuda_runtime.h>

#define C_DIM   64
#define TPB     256
#define MARGIN_F 0.01f
#define MAX_BLOCKS 8192

using u64 = unsigned long long;

// ---- compile-time weights ----
__host__ __device__ constexpr float W2f(int i)  { return 0.5f / (float)(C_DIM - i); }
__host__ __device__ constexpr float CPXf(int x) { return -(W2f(x + 1) + W2f(63 - x)); }
__host__ __device__ constexpr float W2SUMf() {
    float s = 0.0f;
    for (int i = 1; i < C_DIM; i++) s += W2f(i);
    return s;
}

__device__ float        g_partials[MAX_BLOCKS];
__device__ unsigned int g_sem = 0;

// ---- packed f32x2 helpers on float2 (keeps scalar halves addressable) ----
union F2U { float2 f; u64 u; };

__device__ __forceinline__ float2 fma2f(float2 a, float2 b, float2 c) {
    F2U ua, ub, uc, ur;
    ua.f = a; ub.f = b; uc.f = c;
    asm("fma.rn.f32x2 %0, %1, %2, %3;" : "=l"(ur.u) : "l"(ua.u), "l"(ub.u), "l"(uc.u));
    return ur.f;
}
__device__ __forceinline__ float2 add2f(float2 a, float2 b) {
    F2U ua, ub, ur;
    ua.f = a; ub.f = b;
    asm("add.rn.f32x2 %0, %1, %2;" : "=l"(ur.u) : "l"(ua.u), "l"(ub.u));
    return ur.f;
}
__device__ __forceinline__ float2 abs2f(float2 a) {
    F2U ua, ur;
    ua.f = a;
    asm("and.b64 %0, %1, 0x7FFFFFFF7FFFFFFF;" : "=l"(ur.u) : "l"(ua.u));
    return ur.f;
}

__global__ void __launch_bounds__(TPB, 2)
margin_loss_kernel(const float* __restrict__ cand,
                   const float* __restrict__ summ,
                   float* __restrict__ out,
                   int B, float invB)
{
    const int row = blockIdx.x * TPB + threadIdx.x;

    float total = 0.0f;

    if (row < B) {
        float2 V[C_DIM / 2];

        const float4* rp = reinterpret_cast<const float4*>(cand + (size_t)row * C_DIM);
        const float s = summ[row];

        float sa = 0.0f;   // sum |cs - s|
        float p  = 0.0f;   // prefix sum of margin-folded values
        float an = 0.0f;   // telescoped analytic accumulator

        // ---- load + summary-abs + margin-fold + prefix, streamed ----
        #pragma unroll
        for (int i = 0; i < C_DIM / 4; i++) {
            float4 v = rp[i];
            float e[4] = { v.x, v.y, v.z, v.w };
            #pragma unroll
            for (int k = 0; k < 4; k++) {
                const int x = 4 * i + k;
                sa += fabsf(e[k] - s);                          // FADD + FADD|.|
                e[k] = __fmaf_rn(MARGIN_F, (float)x, e[k]);     // fold margin
                p += e[k];
                if (x < 63)
                    an = __fmaf_rn(CPXf(x), p, an);             // FFMA-imm
            }
            V[2 * i]     = make_float2(e[0], e[1]);
            V[2 * i + 1] = make_float2(e[2], e[3]);
        }

        // ---- analytic parts ----
        const float MOFF = 20.16f;   // sum_{x} 0.01*x
        total  = (sa + (p - MOFF) - 64.0f * s) * (0.5f / 64.0f);  // summary term
        total += an;
        total  = __fmaf_rn(p, W2SUMf(), total);                   // telescope

        const float2 NEG1 = make_float2(-1.0f, -1.0f);

        // ---- even gaps i = 2m: packed |V[g+m] - V[g]| ----
        #pragma unroll
        for (int m = 1; m < 32; m++) {
            float2 acc0 = make_float2(0.0f, 0.0f);
            float2 acc1 = make_float2(0.0f, 0.0f);
            #pragma unroll
            for (int g = 0; g + m < 32; g += 2) {
                acc0 = add2f(acc0, abs2f(fma2f(V[g], NEG1, V[g + m])));
                if (g + 1 + m < 32)
                    acc1 = add2f(acc1, abs2f(fma2f(V[g + 1], NEG1, V[g + 1 + m])));
            }
            float gsum = (acc0.x + acc0.y) + (acc1.x + acc1.y);
            total = __fmaf_rn(gsum, W2f(2 * m), total);           // FFMA-imm
        }

        // ---- odd gaps: scalar, |d| folded into FADD operand modifier ----
        // NOTE: macro parameter must not be named 'x' or 'y' (member access!)
        #define A_(idx) (((idx) & 1) ? V[(idx) >> 1].y : V[(idx) >> 1].x)
        #pragma unroll
        for (int i = 1; i < C_DIM; i += 2) {
            float c0 = 0.0f, c1 = 0.0f, c2 = 0.0f;
            #pragma unroll
            for (int j = 0; j + i < C_DIM; j += 3) {
                c0 += fabsf(A_(j + i) - A_(j));
                if (j + 1 + i < C_DIM) c1 += fabsf(A_(j + 1 + i) - A_(j + 1));
                if (j + 2 + i < C_DIM) c2 += fabsf(A_(j + 2 + i) - A_(j + 2));
            }
            total = __fmaf_rn((c0 + c1) + c2, W2f(i), total);     // FFMA-imm
        }
        #undef A_
    }

    // ---- deterministic block reduction ----
    __shared__ float sred[TPB];
    __shared__ bool  amLast;
    sred[threadIdx.x] = total;
    __syncthreads();
    #pragma unroll
    for (int off = TPB / 2; off > 0; off >>= 1) {
        if (threadIdx.x < off)
            sred[threadIdx.x] += sred[threadIdx.x + off];
        __syncthreads();
    }
    if (threadIdx.x == 0) {
        g_partials[blockIdx.x] = sred[0];
        __threadfence();
        unsigned int v = atomicAdd(&g_sem, 1u);
        amLast = (v == gridDim.x - 1);
    }
    __syncthreads();

    // ---- last arriving block: deterministic final reduce ----
    if (amLast) {
        float v = 0.0f;
        for (int i = threadIdx.x; i < (int)gridDim.x; i += TPB)
            v += g_partials[i];
        sred[threadIdx.x] = v;
        __syncthreads();
        #pragma unroll
        for (int off = TPB / 2; off > 0; off >>= 1) {
            if (threadIdx.x < off)
                sred[threadIdx.x] += sred[threadIdx.x + off];
            __syncthreads();
        }
        if (threadIdx.x == 0) {
            out[0] = sred[0] * invB;
            g_sem = 0;   // reset for next graph replay
        }
    }
}

extern "C" void kernel_launch(void* const* d_in, const int* in_sizes, int n_in,
                              void* d_out, int out_size)
{
    const float* cand = (const float*)d_in[0];   // [B, 64] f32
    const float* summ = (const float*)d_in[1];   // [B]     f32
    float* out = (float*)d_out;

    const int B = in_sizes[1];
    int nblocks = (B + TPB - 1) / TPB;
    if (nblocks > MAX_BLOCKS) nblocks = MAX_BLOCKS;
    const float invB = 1.0f / (float)B;

    margin_loss_kernel<<<nblocks, TPB>>>(cand, summ, out, B, invB);
}